// round 14
// baseline (speedup 1.0000x reference)
#include <cuda_runtime.h>
#include <cuda_bf16.h>

// NeuMIP v1, round 14: warp-parity dual-port weight streaming.
//  Even warps: depth MLP + rw0 from __constant__ (LDC), rw1+rw2 from smem.
//  Odd warps:  ow1+ow2 from smem, everything else from __constant__.
//  -> at ANY instant ~half the warps use the LDC port, half the L1 port,
//     regardless of phase alignment (the R13 failure mode).
//  Each inner loop is pure single-port (R7-style). 1 pt/thread, ~80 regs,
//  24 warps/SM. Port budgets/SM: LDC ~304K cyc, L1 ~318K, FMA ~265K.

#define RESOL 512
#define RMASK 511
#define HID 32
#define NSLOPE 0.01f
#define THREADS 256

typedef unsigned long long ull;

// Constant image: ALL layer weights transposed (packed neuron pairs),
// all biases, head weights.
struct __align__(16) CWL {
    ulonglong2 ow0T[10 * 8];
    ulonglong2 ow1T[32 * 8];
    ulonglong2 ow2T[32 * 8];
    ulonglong2 rw0T[12 * 8];
    ulonglong2 rw1T[32 * 8];
    ulonglong2 rw2T[32 * 8];
    ull ob0[16]; ull ob1[16]; ull ob2[16];
    ull rb0[16]; ull rb1[16]; ull rb2[16];
    ull ow3[16];
    ull rw3[3][16];
    float ob3; float rb3[3];
};

__constant__ CWL cw;
__device__ CWL g_stage;

// Shared image: ow1/ow2/rw1/rw2 transposed [32][32].
struct __align__(16) SWS {
    float ow1T[32 * 32];
    float ow2T[32 * 32];
    float rw1T[32 * 32];
    float rw2T[32 * 32];
};

__device__ __forceinline__ float leaky(float x) {
    return fmaxf(x, NSLOPE * x);  // slope < 1
}

__device__ __forceinline__ ull fma2(ull a, ull b, ull c) {
    ull d;
    asm("fma.rn.f32x2 %0, %1, %2, %3;" : "=l"(d) : "l"(a), "l"(b), "l"(c));
    return d;
}

__device__ __forceinline__ ull pack2(float lo, float hi) {
    ull d;
    asm("mov.b64 %0, {%1, %2};" : "=l"(d) : "f"(lo), "f"(hi));
    return d;
}

__device__ __forceinline__ void unpack2(ull v, float& lo, float& hi) {
    asm("mov.b64 {%0, %1}, %2;" : "=f"(lo), "=f"(hi) : "l"(v));
}

// ---------------- prep kernel: build constant staging ----------------

__device__ __forceinline__ void d_tpose(float* dstf, const float* src,
                                        int K, int tid, int nt) {
    for (int idx = tid; idx < K * 32; idx += nt) {
        int i = idx / 32, j = idx - i * 32;
        dstf[idx] = src[j * K + i];
    }
}

__device__ __forceinline__ void d_copy(float* dst, const float* src, int n,
                                       int tid, int nt) {
    for (int i = tid; i < n; i += nt) dst[i] = src[i];
}

__global__ void prep_kernel(const float* ow0, const float* ob0,
                            const float* ow1, const float* ob1,
                            const float* ow2, const float* ob2,
                            const float* ow3, const float* ob3,
                            const float* rw0, const float* rb0,
                            const float* rw1, const float* rb1,
                            const float* rw2, const float* rb2,
                            const float* rw3, const float* rb3) {
    const int tid = threadIdx.x, nt = blockDim.x;
    d_tpose((float*)g_stage.ow0T, ow0, 10, tid, nt);
    d_tpose((float*)g_stage.ow1T, ow1, 32, tid, nt);
    d_tpose((float*)g_stage.ow2T, ow2, 32, tid, nt);
    d_tpose((float*)g_stage.rw0T, rw0, 12, tid, nt);
    d_tpose((float*)g_stage.rw1T, rw1, 32, tid, nt);
    d_tpose((float*)g_stage.rw2T, rw2, 32, tid, nt);
    d_copy((float*)g_stage.ob0, ob0, 32, tid, nt);
    d_copy((float*)g_stage.ob1, ob1, 32, tid, nt);
    d_copy((float*)g_stage.ob2, ob2, 32, tid, nt);
    d_copy((float*)g_stage.rb0, rb0, 32, tid, nt);
    d_copy((float*)g_stage.rb1, rb1, 32, tid, nt);
    d_copy((float*)g_stage.rb2, rb2, 32, tid, nt);
    d_copy((float*)g_stage.ow3, ow3, 32, tid, nt);
    d_copy((float*)g_stage.rw3, rw3, 96, tid, nt);
    if (tid == 0) {
        g_stage.ob3 = ob3[0];
        g_stage.rb3[0] = rb3[0];
        g_stage.rb3[1] = rb3[1];
        g_stage.rb3[2] = rb3[2];
    }
}

// ---------------- main kernel ----------------

// transposed into smem: dst[i*32 + j] = src[j*32 + i]  (K = 32)
__device__ __forceinline__ void tcopy32(float* dst, const float* src,
                                        int tid, int nt) {
    for (int idx = tid; idx < 32 * 32; idx += nt) {
        int i = idx >> 5, j = idx & 31;
        dst[idx] = src[j * 32 + i];
    }
}

// 8-channel bilinear with wrap. Texel = 8 contiguous floats = 2x float4.
__device__ __forceinline__ void bilin8(const float4* __restrict__ t,
                                       float u, float v, float* __restrict__ o) {
    float px = u * (float)RESOL - 0.5f;
    float py = v * (float)RESOL - 0.5f;
    float fpx = floorf(px), fpy = floorf(py);
    float fx = px - fpx, fy = py - fpy;
    int ix = (int)fpx, iy = (int)fpy;
    int x0 = ix & RMASK, x1 = (ix + 1) & RMASK;
    int y0 = iy & RMASK, y1 = (iy + 1) & RMASK;
    float w00 = (1.0f - fx) * (1.0f - fy);
    float w01 = fx * (1.0f - fy);
    float w10 = (1.0f - fx) * fy;
    float w11 = fx * fy;
    const float4* p00 = t + (size_t)(y0 * RESOL + x0) * 2;
    const float4* p01 = t + (size_t)(y0 * RESOL + x1) * 2;
    const float4* p10 = t + (size_t)(y1 * RESOL + x0) * 2;
    const float4* p11 = t + (size_t)(y1 * RESOL + x1) * 2;
    float4 a00 = __ldg(p00),     b00 = __ldg(p00 + 1);
    float4 a01 = __ldg(p01),     b01 = __ldg(p01 + 1);
    float4 a10 = __ldg(p10),     b10 = __ldg(p10 + 1);
    float4 a11 = __ldg(p11),     b11 = __ldg(p11 + 1);
    o[0] = w00 * a00.x + w01 * a01.x + w10 * a10.x + w11 * a11.x;
    o[1] = w00 * a00.y + w01 * a01.y + w10 * a10.y + w11 * a11.y;
    o[2] = w00 * a00.z + w01 * a01.z + w10 * a10.z + w11 * a11.z;
    o[3] = w00 * a00.w + w01 * a01.w + w10 * a10.w + w11 * a11.w;
    o[4] = w00 * b00.x + w01 * b01.x + w10 * b10.x + w11 * b11.x;
    o[5] = w00 * b00.y + w01 * b01.y + w10 * b10.y + w11 * b11.y;
    o[6] = w00 * b00.z + w01 * b01.z + w10 * b10.z + w11 * b11.z;
    o[7] = w00 * b00.w + w01 * b01.w + w10 * b10.w + w11 * b11.w;
}

// Pure-constant layer: all 32 neurons, 8 LDC.128 per input row.
template <int K>
__device__ __forceinline__ void layerC(const ulonglong2* __restrict__ wT,
                                       const ull* __restrict__ bias,
                                       const float* __restrict__ in,
                                       float* __restrict__ out) {
    ull acc[16];
#pragma unroll
    for (int k = 0; k < 16; k++) acc[k] = bias[k];
#pragma unroll
    for (int i = 0; i < K; i++) {
        ull a = pack2(in[i], in[i]);
#pragma unroll
        for (int q = 0; q < 8; q++) {
            ulonglong2 w = wT[i * 8 + q];
            acc[2 * q]     = fma2(a, w.x, acc[2 * q]);
            acc[2 * q + 1] = fma2(a, w.y, acc[2 * q + 1]);
        }
    }
#pragma unroll
    for (int k = 0; k < 16; k++) {
        float x, y;
        unpack2(acc[k], x, y);
        out[2 * k]     = leaky(x);
        out[2 * k + 1] = leaky(y);
    }
}

// Pure-smem layer: all 32 neurons, 8 warp-uniform LDS.128 per input row.
__device__ __forceinline__ void layerS(const float* __restrict__ wT,
                                       const ull* __restrict__ bias,
                                       const float* __restrict__ in,
                                       float* __restrict__ out) {
    ull acc[16];
#pragma unroll
    for (int k = 0; k < 16; k++) acc[k] = bias[k];
#pragma unroll
    for (int i = 0; i < HID; i++) {
        ull a = pack2(in[i], in[i]);
        const ulonglong2* w2 = reinterpret_cast<const ulonglong2*>(wT + i * HID);
#pragma unroll
        for (int q = 0; q < 8; q++) {
            ulonglong2 w = w2[q];
            acc[2 * q]     = fma2(a, w.x, acc[2 * q]);
            acc[2 * q + 1] = fma2(a, w.y, acc[2 * q + 1]);
        }
    }
#pragma unroll
    for (int k = 0; k < 16; k++) {
        float x, y;
        unpack2(acc[k], x, y);
        out[2 * k]     = leaky(x);
        out[2 * k + 1] = leaky(y);
    }
}

__device__ __forceinline__ float dotC(const ull* __restrict__ w,
                                      const float* __restrict__ v) {
    ull acc = pack2(0.0f, 0.0f);
#pragma unroll
    for (int k = 0; k < 16; k++) {
        acc = fma2(pack2(v[2 * k], v[2 * k + 1]), w[k], acc);
    }
    float lo, hi;
    unpack2(acc, lo, hi);
    return lo + hi;
}

__global__ void __launch_bounds__(THREADS, 3)
neumip_kernel(const float* __restrict__ cam,
              const float* __restrict__ light,
              const float* __restrict__ uv,
              const float* __restrict__ offset_tex,
              const float* __restrict__ rgb_tex,
              const float* __restrict__ ow1, const float* __restrict__ ow2,
              const float* __restrict__ rw1, const float* __restrict__ rw2,
              float* __restrict__ out, int n) {
    __shared__ SWS s;
    const int tid = threadIdx.x;
    tcopy32(s.ow1T, ow1, tid, THREADS);
    tcopy32(s.ow2T, ow2, tid, THREADS);
    tcopy32(s.rw1T, rw1, tid, THREADS);
    tcopy32(s.rw2T, rw2, tid, THREADS);
    __syncthreads();

    const int p = blockIdx.x * blockDim.x + tid;
    if (p >= n) return;

    const int wpar = (tid >> 5) & 1;  // warp parity: port assignment

    const float2 c2 = __ldg(reinterpret_cast<const float2*>(cam) + p);
    const float2 t2 = __ldg(reinterpret_cast<const float2*>(uv) + p);
    const float cx = c2.x, cy = c2.y;
    const float u0 = t2.x, v0 = t2.y;

    // ---- offset texture gather + depth MLP ----
    float in[12];
    bilin8(reinterpret_cast<const float4*>(offset_tex), u0, v0, in);
    in[8] = cx;
    in[9] = cy;

    float ha[HID], hb[HID];
    layerC<10>(cw.ow0T, cw.ob0, in, ha);
    if (wpar == 0) {
        layerC<HID>(cw.ow1T, cw.ob1, ha, hb);   // const port
        layerC<HID>(cw.ow2T, cw.ob2, hb, ha);
    } else {
        layerS(s.ow1T, cw.ob1, ha, hb);         // smem port
        layerS(s.ow2T, cw.ob2, hb, ha);
    }

    float depth = dotC(cw.ow3, ha) + cw.ob3;

    // ---- parallax offset ----
    float z = sqrtf(fmaxf(1.0f - (cx * cx + cy * cy), 1e-6f));
    float sc = depth / z;
    float u1 = u0 + cx * sc;
    float v1 = v0 + cy * sc;

    // ---- rgb texture gather + rgb MLP ----
    const float2 l2 = __ldg(reinterpret_cast<const float2*>(light) + p);
    in[0] = l2.x;
    in[1] = l2.y;
    in[2] = cx;
    in[3] = cy;
    bilin8(reinterpret_cast<const float4*>(rgb_tex), u1, v1, in + 4);

    layerC<12>(cw.rw0T, cw.rb0, in, ha);
    if (wpar == 0) {
        layerS(s.rw1T, cw.rb1, ha, hb);         // smem port
        layerS(s.rw2T, cw.rb2, hb, ha);
    } else {
        layerC<HID>(cw.rw1T, cw.rb1, ha, hb);   // const port
        layerC<HID>(cw.rw2T, cw.rb2, hb, ha);
    }

    out[3 * p + 0] = dotC(cw.rw3[0], ha) + cw.rb3[0];
    out[3 * p + 1] = dotC(cw.rw3[1], ha) + cw.rb3[1];
    out[3 * p + 2] = dotC(cw.rw3[2], ha) + cw.rb3[2];
}

extern "C" void kernel_launch(void* const* d_in, const int* in_sizes, int n_in,
                              void* d_out, int out_size) {
    const float* cam        = (const float*)d_in[0];
    const float* light      = (const float*)d_in[1];
    const float* uv         = (const float*)d_in[2];
    const float* offset_tex = (const float*)d_in[3];
    const float* rgb_tex    = (const float*)d_in[4];

    // 1) pack/transpose all weights + biases into device staging
    prep_kernel<<<1, 256>>>((const float*)d_in[5],  (const float*)d_in[6],
                            (const float*)d_in[7],  (const float*)d_in[8],
                            (const float*)d_in[9],  (const float*)d_in[10],
                            (const float*)d_in[11], (const float*)d_in[12],
                            (const float*)d_in[13], (const float*)d_in[14],
                            (const float*)d_in[15], (const float*)d_in[16],
                            (const float*)d_in[17], (const float*)d_in[18],
                            (const float*)d_in[19], (const float*)d_in[20]);

    // 2) device-to-device copy into the __constant__ image (capturable)
    void* stage_ptr = nullptr;
    cudaGetSymbolAddress(&stage_ptr, g_stage);
    cudaMemcpyToSymbolAsync(cw, stage_ptr, sizeof(CWL), 0,
                            cudaMemcpyDeviceToDevice, 0);

    // 3) main kernel (smem layers transposed from global at block start)
    const int n = in_sizes[0] / 2;  // camera_dir is (B, 2)
    const int blocks = (n + THREADS - 1) / THREADS;
    neumip_kernel<<<blocks, THREADS>>>(cam, light, uv, offset_tex, rgb_tex,
                                       (const float*)d_in[7],
                                       (const float*)d_in[9],
                                       (const float*)d_in[15],
                                       (const float*)d_in[17],
                                       (float*)d_out, n);
}

// round 15
// speedup vs baseline: 1.3728x; 1.3728x over previous
#include <cuda_runtime.h>
#include <cuda_bf16.h>

// NeuMIP v1, round 15: 2 pts/thread + all-const weights (R8 traffic: LDC
// halved to ~127us/SM) + activations in per-thread SMEM columns instead of
// registers (fixes R8's 148-reg latency bind; ~105 regs -> 16 warps/SM).
// Channel c of (pt0,pt1) stored as one float2 -> packed f32x2 heads for free.

#define RESOL 512
#define RMASK 511
#define HID 32
#define NSLOPE 0.01f
#define THREADS 128
#define PTS_PER_BLOCK 256

typedef unsigned long long ull;

// Constant image: transposed weights [K][32] packed neuron pairs; biases;
// head weights duplicated per-lane for packed f32x2 dot products.
struct __align__(16) CW {
    ulonglong2 ow0T[10 * 8];
    ulonglong2 ow1T[32 * 8];
    ulonglong2 ow2T[32 * 8];
    ulonglong2 rw0T[12 * 8];
    ulonglong2 rw1T[32 * 8];
    ulonglong2 rw2T[32 * 8];
    ull ob0[16]; ull ob1[16]; ull ob2[16];
    ull rb0[16]; ull rb1[16]; ull rb2[16];
    ull ow3d[32];        // (w_i, w_i) duplicated pairs
    ull rw3d[3][32];
    float ob3; float rb3[3];
};

__constant__ CW cw;
__device__ CW g_stage;

__device__ __forceinline__ float leaky(float x) {
    return fmaxf(x, NSLOPE * x);  // slope < 1
}

__device__ __forceinline__ ull fma2(ull a, ull b, ull c) {
    ull d;
    asm("fma.rn.f32x2 %0, %1, %2, %3;" : "=l"(d) : "l"(a), "l"(b), "l"(c));
    return d;
}

__device__ __forceinline__ ull pack2(float lo, float hi) {
    ull d;
    asm("mov.b64 %0, {%1, %2};" : "=l"(d) : "f"(lo), "f"(hi));
    return d;
}

__device__ __forceinline__ void unpack2(ull v, float& lo, float& hi) {
    asm("mov.b64 {%0, %1}, %2;" : "=f"(lo), "=f"(hi) : "l"(v));
}

// ---------------- prep kernel ----------------

__device__ __forceinline__ void d_tpose(float* dstf, const float* src,
                                        int K, int tid, int nt) {
    // src [32][K] -> dst [K][32]
    for (int idx = tid; idx < K * 32; idx += nt) {
        int i = idx / 32, j = idx - i * 32;
        dstf[idx] = src[j * K + i];
    }
}

__device__ __forceinline__ void d_copy(float* dst, const float* src, int n,
                                       int tid, int nt) {
    for (int i = tid; i < n; i += nt) dst[i] = src[i];
}

__device__ __forceinline__ ull dup2(float w) {
    unsigned u = __float_as_uint(w);
    return ((ull)u << 32) | u;
}

__global__ void prep_kernel(const float* ow0, const float* ob0,
                            const float* ow1, const float* ob1,
                            const float* ow2, const float* ob2,
                            const float* ow3, const float* ob3,
                            const float* rw0, const float* rb0,
                            const float* rw1, const float* rb1,
                            const float* rw2, const float* rb2,
                            const float* rw3, const float* rb3) {
    const int tid = threadIdx.x, nt = blockDim.x;
    d_tpose((float*)g_stage.ow0T, ow0, 10, tid, nt);
    d_tpose((float*)g_stage.ow1T, ow1, 32, tid, nt);
    d_tpose((float*)g_stage.ow2T, ow2, 32, tid, nt);
    d_tpose((float*)g_stage.rw0T, rw0, 12, tid, nt);
    d_tpose((float*)g_stage.rw1T, rw1, 32, tid, nt);
    d_tpose((float*)g_stage.rw2T, rw2, 32, tid, nt);
    d_copy((float*)g_stage.ob0, ob0, 32, tid, nt);
    d_copy((float*)g_stage.ob1, ob1, 32, tid, nt);
    d_copy((float*)g_stage.ob2, ob2, 32, tid, nt);
    d_copy((float*)g_stage.rb0, rb0, 32, tid, nt);
    d_copy((float*)g_stage.rb1, rb1, 32, tid, nt);
    d_copy((float*)g_stage.rb2, rb2, 32, tid, nt);
    for (int i = tid; i < 32; i += nt) {
        g_stage.ow3d[i] = dup2(ow3[i]);
        g_stage.rw3d[0][i] = dup2(rw3[0 * 32 + i]);
        g_stage.rw3d[1][i] = dup2(rw3[1 * 32 + i]);
        g_stage.rw3d[2][i] = dup2(rw3[2 * 32 + i]);
    }
    if (tid == 0) {
        g_stage.ob3 = ob3[0];
        g_stage.rb3[0] = rb3[0];
        g_stage.rb3[1] = rb3[1];
        g_stage.rb3[2] = rb3[2];
    }
}

// ---------------- main kernel ----------------

// 8-channel bilinear with wrap.
__device__ __forceinline__ void bilin8(const float4* __restrict__ t,
                                       float u, float v, float* __restrict__ o) {
    float px = u * (float)RESOL - 0.5f;
    float py = v * (float)RESOL - 0.5f;
    float fpx = floorf(px), fpy = floorf(py);
    float fx = px - fpx, fy = py - fpy;
    int ix = (int)fpx, iy = (int)fpy;
    int x0 = ix & RMASK, x1 = (ix + 1) & RMASK;
    int y0 = iy & RMASK, y1 = (iy + 1) & RMASK;
    float w00 = (1.0f - fx) * (1.0f - fy);
    float w01 = fx * (1.0f - fy);
    float w10 = (1.0f - fx) * fy;
    float w11 = fx * fy;
    const float4* p00 = t + (size_t)(y0 * RESOL + x0) * 2;
    const float4* p01 = t + (size_t)(y0 * RESOL + x1) * 2;
    const float4* p10 = t + (size_t)(y1 * RESOL + x0) * 2;
    const float4* p11 = t + (size_t)(y1 * RESOL + x1) * 2;
    float4 a00 = __ldg(p00),     b00 = __ldg(p00 + 1);
    float4 a01 = __ldg(p01),     b01 = __ldg(p01 + 1);
    float4 a10 = __ldg(p10),     b10 = __ldg(p10 + 1);
    float4 a11 = __ldg(p11),     b11 = __ldg(p11 + 1);
    o[0] = w00 * a00.x + w01 * a01.x + w10 * a10.x + w11 * a11.x;
    o[1] = w00 * a00.y + w01 * a01.y + w10 * a10.y + w11 * a11.y;
    o[2] = w00 * a00.z + w01 * a01.z + w10 * a10.z + w11 * a11.z;
    o[3] = w00 * a00.w + w01 * a01.w + w10 * a10.w + w11 * a11.w;
    o[4] = w00 * b00.x + w01 * b01.x + w10 * b10.x + w11 * b11.x;
    o[5] = w00 * b00.y + w01 * b01.y + w10 * b10.y + w11 * b11.y;
    o[6] = w00 * b00.z + w01 * b01.z + w10 * b10.z + w11 * b11.z;
    o[7] = w00 * b00.w + w01 * b01.w + w10 * b10.w + w11 * b11.w;
}

// One layer, 2 points per thread. Inputs read from this thread's smem column
// (float2 = (pt0,pt1) per channel), outputs written back in place.
// Weights: 8 LDC.128 per input row (serves both points).
template <int K>
__device__ __forceinline__ void layerC2S(const ulonglong2* __restrict__ wT,
                                         const ull* __restrict__ bias,
                                         float2* __restrict__ col) {
    ull acc0[16], acc1[16];
#pragma unroll
    for (int k = 0; k < 16; k++) { ull b = bias[k]; acc0[k] = b; acc1[k] = b; }
#pragma unroll
    for (int i = 0; i < K; i++) {
        float2 v = col[i * THREADS];
        ull a0 = pack2(v.x, v.x);
        ull a1 = pack2(v.y, v.y);
#pragma unroll
        for (int q = 0; q < 8; q++) {
            ulonglong2 w = wT[i * 8 + q];
            acc0[2 * q]     = fma2(a0, w.x, acc0[2 * q]);
            acc0[2 * q + 1] = fma2(a0, w.y, acc0[2 * q + 1]);
            acc1[2 * q]     = fma2(a1, w.x, acc1[2 * q]);
            acc1[2 * q + 1] = fma2(a1, w.y, acc1[2 * q + 1]);
        }
    }
#pragma unroll
    for (int k = 0; k < 16; k++) {
        float x0, y0, x1, y1;
        unpack2(acc0[k], x0, y0);   // pt0: neurons 2k, 2k+1
        unpack2(acc1[k], x1, y1);   // pt1: neurons 2k, 2k+1
        col[(2 * k) * THREADS]     = make_float2(leaky(x0), leaky(x1));
        col[(2 * k + 1) * THREADS] = make_float2(leaky(y0), leaky(y1));
    }
}

// Packed head: returns (dot_pt0, dot_pt1) via f32x2 over the smem column.
__device__ __forceinline__ ull head2(const ull* __restrict__ wd,
                                     const float2* __restrict__ col) {
    const ull* colu = reinterpret_cast<const ull*>(col);
    ull acc = pack2(0.0f, 0.0f);
#pragma unroll
    for (int i = 0; i < 32; i++)
        acc = fma2(colu[i * THREADS], wd[i], acc);
    return acc;
}

__global__ void __launch_bounds__(THREADS, 4)
neumip_kernel(const float* __restrict__ cam,
              const float* __restrict__ light,
              const float* __restrict__ uv,
              const float* __restrict__ offset_tex,
              const float* __restrict__ rgb_tex,
              float* __restrict__ out, int n) {
    __shared__ float2 act[HID][THREADS];   // 32 KB: channel-major, lane-contig
    const int tid = threadIdx.x;
    float2* col = &act[0][tid];

    const int p0 = blockIdx.x * PTS_PER_BLOCK + tid;
    const int p1 = p0 + THREADS;
    if (p0 >= n) return;
    const int p1c = p1 < n ? p1 : p0;   // clamp (n is a multiple of 256 anyway)

    const float2* cam2 = reinterpret_cast<const float2*>(cam);
    const float2* uv2p = reinterpret_cast<const float2*>(uv);
    const float2* li2 = reinterpret_cast<const float2*>(light);

    const float2 c0 = __ldg(cam2 + p0);
    const float2 c1 = __ldg(cam2 + p1c);
    const float2 t0 = __ldg(uv2p + p0);
    const float2 t1 = __ldg(uv2p + p1c);

    // ---- offset gathers -> smem channels 0..9 ----
    {
        float la[8], lb[8];
        bilin8(reinterpret_cast<const float4*>(offset_tex), t0.x, t0.y, la);
        bilin8(reinterpret_cast<const float4*>(offset_tex), t1.x, t1.y, lb);
#pragma unroll
        for (int c = 0; c < 8; c++) col[c * THREADS] = make_float2(la[c], lb[c]);
        col[8 * THREADS] = make_float2(c0.x, c1.x);
        col[9 * THREADS] = make_float2(c0.y, c1.y);
    }

    // ---- depth MLP ----
    layerC2S<10>(cw.ow0T, cw.ob0, col);
    layerC2S<HID>(cw.ow1T, cw.ob1, col);
    layerC2S<HID>(cw.ow2T, cw.ob2, col);

    float dep0, dep1;
    {
        ull d = head2(cw.ow3d, col);
        unpack2(d, dep0, dep1);
        dep0 += cw.ob3;
        dep1 += cw.ob3;
    }

    // ---- parallax + rgb gathers -> smem channels 0..11 ----
    {
        float z0 = sqrtf(fmaxf(1.0f - (c0.x * c0.x + c0.y * c0.y), 1e-6f));
        float z1 = sqrtf(fmaxf(1.0f - (c1.x * c1.x + c1.y * c1.y), 1e-6f));
        float s0 = dep0 / z0, s1 = dep1 / z1;
        float u10 = t0.x + c0.x * s0, v10 = t0.y + c0.y * s0;
        float u11 = t1.x + c1.x * s1, v11 = t1.y + c1.y * s1;
        const float2 l0 = __ldg(li2 + p0);
        const float2 l1 = __ldg(li2 + p1c);
        float la[8], lb[8];
        bilin8(reinterpret_cast<const float4*>(rgb_tex), u10, v10, la);
        bilin8(reinterpret_cast<const float4*>(rgb_tex), u11, v11, lb);
        col[0 * THREADS] = make_float2(l0.x, l1.x);
        col[1 * THREADS] = make_float2(l0.y, l1.y);
        col[2 * THREADS] = make_float2(c0.x, c1.x);
        col[3 * THREADS] = make_float2(c0.y, c1.y);
#pragma unroll
        for (int c = 0; c < 8; c++)
            col[(4 + c) * THREADS] = make_float2(la[c], lb[c]);
    }

    // ---- rgb MLP ----
    layerC2S<12>(cw.rw0T, cw.rb0, col);
    layerC2S<HID>(cw.rw1T, cw.rb1, col);
    layerC2S<HID>(cw.rw2T, cw.rb2, col);

    // ---- rgb head (packed over both points) ----
    float o00, o01, o02, o10, o11, o12;
    {
        float a, b;
        unpack2(head2(cw.rw3d[0], col), a, b);
        o00 = a + cw.rb3[0]; o10 = b + cw.rb3[0];
        unpack2(head2(cw.rw3d[1], col), a, b);
        o01 = a + cw.rb3[1]; o11 = b + cw.rb3[1];
        unpack2(head2(cw.rw3d[2], col), a, b);
        o02 = a + cw.rb3[2]; o12 = b + cw.rb3[2];
    }
    out[3 * p0 + 0] = o00;
    out[3 * p0 + 1] = o01;
    out[3 * p0 + 2] = o02;
    if (p1 < n) {
        out[3 * p1 + 0] = o10;
        out[3 * p1 + 1] = o11;
        out[3 * p1 + 2] = o12;
    }
}

extern "C" void kernel_launch(void* const* d_in, const int* in_sizes, int n_in,
                              void* d_out, int out_size) {
    const float* cam        = (const float*)d_in[0];
    const float* light      = (const float*)d_in[1];
    const float* uv         = (const float*)d_in[2];
    const float* offset_tex = (const float*)d_in[3];
    const float* rgb_tex    = (const float*)d_in[4];

    prep_kernel<<<1, 256>>>((const float*)d_in[5],  (const float*)d_in[6],
                            (const float*)d_in[7],  (const float*)d_in[8],
                            (const float*)d_in[9],  (const float*)d_in[10],
                            (const float*)d_in[11], (const float*)d_in[12],
                            (const float*)d_in[13], (const float*)d_in[14],
                            (const float*)d_in[15], (const float*)d_in[16],
                            (const float*)d_in[17], (const float*)d_in[18],
                            (const float*)d_in[19], (const float*)d_in[20]);

    void* stage_ptr = nullptr;
    cudaGetSymbolAddress(&stage_ptr, g_stage);
    cudaMemcpyToSymbolAsync(cw, stage_ptr, sizeof(CW), 0,
                            cudaMemcpyDeviceToDevice, 0);

    const int n = in_sizes[0] / 2;  // camera_dir is (B, 2)
    const int blocks = (n + PTS_PER_BLOCK - 1) / PTS_PER_BLOCK;
    neumip_kernel<<<blocks, THREADS>>>(cam, light, uv, offset_tex, rgb_tex,
                                       (float*)d_out, n);
}